// round 12
// baseline (speedup 1.0000x reference)
#include <cuda_runtime.h>
#include <cstdint>

#define BATCH 65536
#define INP 64
#define HID 128
#define NACT 16
#define BM 64
#define NTHR 512

// smem strides (floats); all ≡ 4 (mod 32) -> conflict-free LDSM row addressing
#define XS 68
#define HS 132
#define WS 36
#define WHS 132

// Layout (floats): sH [64x132] at 0 (sX [64x68] ALIASED; x dead after superchunk 1),
// 3-buffer gate-fused weight ring [384x36] each, head weights, biases.
#define RING_OFF 8448
#define BUF_FLOATS (384 * WS)                   // 13824
#define WH_OFF (RING_OFF + 3 * BUF_FLOATS)      // 49920
#define SB_OFF (WH_OFF + 24 * WHS)              // 53088
#define SMEM_FLOATS (SB_OFF + 6 * 128)          // 53856
#define SMEM_BYTES (SMEM_FLOATS * 4)            // 215424 B -> 1 CTA/SM

__device__ __forceinline__ void cpa16(float* dst, const float* src) {
    unsigned u = (unsigned)__cvta_generic_to_shared(dst);
    asm volatile("cp.async.cg.shared.global [%0], [%1], 16;" ::"r"(u), "l"(src));
}
__device__ __forceinline__ void cpcommit() { asm volatile("cp.async.commit_group;"); }

__device__ __forceinline__ float htanh(float v) {
    float r;
    asm("tanh.approx.f32 %0, %1;" : "=f"(r) : "f"(v));
    return r;
}
__device__ __forceinline__ float fsig(float v) {
    return fmaf(htanh(0.5f * v), 0.5f, 0.5f);
}

#define MMA_TF32(d, a0, a1, a2, a3, b0, b1)                                     \
    asm volatile(                                                               \
        "mma.sync.aligned.m16n8k8.row.col.f32.tf32.tf32.f32 "                   \
        "{%0,%1,%2,%3},{%4,%5,%6,%7},{%8,%9},{%0,%1,%2,%3};"                    \
        : "+f"(d[0]), "+f"(d[1]), "+f"(d[2]), "+f"(d[3])                        \
        : "r"(a0), "r"(a1), "r"(a2), "r"(a3), "r"(b0), "r"(b1))

__device__ __forceinline__ void ldsm4(unsigned r[4], unsigned addr) {
    asm volatile("ldmatrix.sync.aligned.m8n8.x4.shared.b16 {%0,%1,%2,%3}, [%4];"
                 : "=r"(r[0]), "=r"(r[1]), "=r"(r[2]), "=r"(r[3])
                 : "r"(addr));
}

__global__ void __launch_bounds__(NTHR, 1)
lstm_policy_kernel(const float* __restrict__ x,
                   const float* __restrict__ Wih0,
                   const float* __restrict__ bih0,
                   const float* __restrict__ bhh0,
                   const float* __restrict__ Wih1,
                   const float* __restrict__ bih1,
                   const float* __restrict__ bhh1,
                   const float* __restrict__ Wp,
                   const float* __restrict__ bp,
                   const float* __restrict__ Wv,
                   const float* __restrict__ bv,
                   float* __restrict__ out) {
    extern __shared__ float sm[];
    float* sH = sm;              // [64][132] h0
    float* sX = sm;              // [64][68]  x, ALIASED (dead after superchunk 1)
    float* sW = sm + RING_OFF;   // 3 x [384][36] ring
    float* sH1 = sm + RING_OFF;  // h1 plain [64][132] over dead ring buf0
    float* sWH = sm + WH_OFF;
    float* sB = sm + SB_OFF;

    const int tid = threadIdx.x;
    const int wid = tid >> 5, lane = tid & 31;
    const int g = lane >> 2, tg = lane & 3;
    // warp grid: 2 row-groups x 8 col-groups; warp tile 32 rows x 16 cols
    const int mrow = (wid >> 3) * 32;
    const int ncolW = (wid & 7) * 16;
    const int rowbase = blockIdx.x * BM;

    // pair-split slab prefetch for superchunk k (0..5): the pair (wid, wid^8)
    // shares ncolW; member p=wid>>3 loads half of the 384-float4 slab
    // (3 gates x 16 rows x 8 f4). Block barrier after wait publishes all halves.
    auto prefSlab = [&](int k) {
        const float* W = (k < 2) ? Wih0 : Wih1;
        int ld = (k < 2) ? INP : HID;
        int koff = ((k < 2) ? k : (k - 2)) * 32;
        float* dst = sW + (k % 3) * BUF_FLOATS;
        const int p = wid >> 3;
#pragma unroll
        for (int i = 0; i < 6; i++) {
            int idx = p * 192 + lane + i * 32;  // [0,192) or [192,384)
            int gate = idx >> 7;
            int rem = idx & 127;
            int r = rem >> 3, c4 = rem & 7;
            int gbase = (gate == 0) ? 0 : (gate == 1 ? 256 : 384);
            int row = ncolW + r;
            cpa16(dst + (gate * 128 + row) * WS + c4 * 4,
                  W + (size_t)(gbase + row) * ld + koff + c4 * 4);
        }
    };

    // ---- prologue: G0 = {x, head weights}; G1 = {slab0}; G2 = {slab1} ----
    {
        const float* xs = x + (size_t)rowbase * INP;
#pragma unroll
        for (int i = 0; i < 2; i++) {
            int idx = tid + i * NTHR;  // 1024 float4 (64 rows x 16)
            int r = idx >> 4;
            int c4 = idx & 15;
            cpa16(sX + r * XS + c4 * 4, xs + r * INP + c4 * 4);
        }
#pragma unroll
        for (int idx = tid; idx < 544; idx += NTHR) {  // strided! (R2 lesson)
            int r = idx >> 5, c4 = idx & 31;
            const float* srcp = (r < 16) ? (Wp + r * HID + c4 * 4) : (Wv + c4 * 4);
            cpa16(sWH + r * WHS + c4 * 4, srcp);
        }
        cpcommit();      // G0
        prefSlab(0);
        cpcommit();      // G1
        prefSlab(1);
        cpcommit();      // G2
    }

    // combined biases + zero-pad head rows 17..23 (visible after first barrier)
    if (tid < 128) {
        sB[tid] = bih0[tid] + bhh0[tid];
        sB[128 + tid] = bih0[256 + tid] + bhh0[256 + tid];
        sB[256 + tid] = bih0[384 + tid] + bhh0[384 + tid];
        sB[384 + tid] = bih1[tid] + bhh1[tid];
        sB[512 + tid] = bih1[256 + tid] + bhh1[256 + tid];
        sB[640 + tid] = bih1[384 + tid] + bhh1[384 + tid];
    }
#pragma unroll
    for (int idx = tid; idx < 7 * HID; idx += NTHR) {
        int r = 17 + idx / HID, c = idx % HID;
        sWH[r * WHS + c] = 0.f;
    }

    // ---- LDSM address precompute (verified fragment mapping, R7-R9) ----
    const int j8 = lane & 7, sel = lane >> 3;
    const int arow = ((sel & 1) << 3) + j8;
    const int acol = (sel >> 1) << 2;
    const unsigned shBase = (unsigned)__cvta_generic_to_shared(sm);
    const unsigned swBase = shBase + RING_OFF * 4;
    const unsigned aX = shBase + ((mrow + arow) * XS + acol) * 4;
    const unsigned aH = shBase + ((mrow + arow) * HS + acol) * 4;
    const unsigned bO = ((ncolW + ((sel >> 1) << 3) + j8) * WS + ((sel & 1) << 2)) * 4;

    // 3 gate accumulators live across a whole layer: [gate][mt][nt][ci]
    float acc[3][2][2][4];
#pragma unroll
    for (int gt = 0; gt < 3; gt++)
#pragma unroll
        for (int mt = 0; mt < 2; mt++)
#pragma unroll
            for (int nt = 0; nt < 2; nt++)
#pragma unroll
                for (int ci = 0; ci < 4; ci++) acc[gt][mt][nt][ci] = 0.f;

    // one gate-fused superchunk (K=32, all 3 gates): 20 ldsm4, 48 MMA.
    // A fragments loaded ONCE per ks, reused by all 3 gates (the 3x LDS cut).
    auto gemmChunk = [&](unsigned aBase, unsigned pitch, unsigned wbase) {
#pragma unroll
        for (int ks = 0; ks < 4; ks++) {
            unsigned a0[4], a1[4];
            ldsm4(a0, aBase + ks * 32);
            ldsm4(a1, aBase + pitch + ks * 32);
#pragma unroll
            for (int gt = 0; gt < 3; gt++) {
                unsigned bf[4];
                ldsm4(bf, wbase + gt * (128 * WS * 4) + bO + ks * 32);
                MMA_TF32(acc[gt][0][0], a0[0], a0[1], a0[2], a0[3], bf[0], bf[1]);
                MMA_TF32(acc[gt][0][1], a0[0], a0[1], a0[2], a0[3], bf[2], bf[3]);
                MMA_TF32(acc[gt][1][0], a1[0], a1[1], a1[2], a1[3], bf[0], bf[1]);
                MMA_TF32(acc[gt][1][1], a1[0], a1[1], a1[2], a1[3], bf[2], bf[3]);
            }
        }
    };

    // single-pass epilogue straight from the 3 gate accs
    auto epi = [&](int L) {
#pragma unroll
        for (int mt = 0; mt < 2; mt++)
#pragma unroll
            for (int nt = 0; nt < 2; nt++)
#pragma unroll
                for (int ci = 0; ci < 4; ci++) {
                    int row = mrow + mt * 16 + g + ((ci >> 1) << 3);
                    int cc = ncolW + nt * 8 + (tg << 1) + (ci & 1);
                    float iv = acc[0][mt][nt][ci] + sB[L * 384 + cc];
                    float gv = acc[1][mt][nt][ci] + sB[L * 384 + 128 + cc];
                    float ov = acc[2][mt][nt][ci] + sB[L * 384 + 256 + cc];
                    float h = fsig(ov) * htanh(fsig(iv) * htanh(gv));
                    if (L == 0)
                        sH[row * HS + cc] = h;
                    else
                        sH1[row * HS + cc] = h;
                    acc[0][mt][nt][ci] = 0.f;
                    acc[1][mt][nt][ci] = 0.f;
                    acc[2][mt][nt][ci] = 0.f;
                }
    };

    // ---- pipeline: per chunk k: wait_group 1 -> __syncthreads -> prefetch(k+2)
    //      -> gemm(k).  Barrier publishes all warps' slab halves AND orders
    //      buffer reuse (buf (k+2)%3 was last read at gemm(k-1)). ----

    // k=0 (also covers prologue G0 visibility: wait_group 1 => G0,G1 done)
    asm volatile("cp.async.wait_group 1;");
    __syncthreads();  // BARRIER 1: x, sWH, sB, slab0 visible
    prefSlab(2);
    cpcommit();  // G3 -> buf2
    gemmChunk(aX, 16 * XS * 4, swBase);
    // k=1
    asm volatile("cp.async.wait_group 1;");
    __syncthreads();  // slab1 visible; buf0 reads (gemm0) done block-wide
    prefSlab(3);
    cpcommit();  // G4 -> buf0
    gemmChunk(aX + 128, 16 * XS * 4, swBase + BUF_FLOATS * 4);

    // ---- layer boundary: h0 overwrites aliased sX ----
    __syncthreads();  // BARRIER: all warps done reading x
    epi(0);           // h0 -> sH
    __syncthreads();  // h0 visible to all warps

    // k=2
    asm volatile("cp.async.wait_group 1;");
    __syncthreads();  // slab2 visible; buf1 reads (gemm1) done
    prefSlab(4);
    cpcommit();  // G5 -> buf1
    gemmChunk(aH, 16 * HS * 4, swBase + 2 * BUF_FLOATS * 4);
    // k=3
    asm volatile("cp.async.wait_group 1;");
    __syncthreads();  // slab3 visible; buf2 reads (gemm2) done
    prefSlab(5);
    cpcommit();  // G6 -> buf2
    gemmChunk(aH + 128, 16 * HS * 4, swBase);
    // k=4
    asm volatile("cp.async.wait_group 1;");
    __syncthreads();  // slab4 visible
    gemmChunk(aH + 256, 16 * HS * 4, swBase + BUF_FLOATS * 4);
    // k=5
    asm volatile("cp.async.wait_group 0;");
    __syncthreads();  // slab5 visible
    gemmChunk(aH + 384, 16 * HS * 4, swBase + 2 * BUF_FLOATS * 4);

    __syncthreads();  // all warps done reading ring weights + h0
    epi(1);           // h1 -> plain [64][132] over dead ring buf0
    __syncthreads();  // h1 visible

    // ---- heads on tensor cores (warps 0..3; proven code) ----
    float* pol = out;
    float* val = out + (size_t)BATCH * NACT;
    if (wid < 4) {
        float ha[3][4];
#pragma unroll
        for (int nt = 0; nt < 3; nt++)
#pragma unroll
            for (int ci = 0; ci < 4; ci++) ha[nt][ci] = 0.f;
        const unsigned* uA = (const unsigned*)sH1;
        const unsigned* uW = (const unsigned*)sWH;
        const int mrowH = wid * 16;
#pragma unroll
        for (int ks = 0; ks < 16; ks++) {
            const unsigned* bA = uA + (mrowH + g) * HS + ks * 8 + tg;
            unsigned a0 = bA[0], a1 = bA[8 * HS], a2 = bA[4], a3 = bA[8 * HS + 4];
#pragma unroll
            for (int nt = 0; nt < 3; nt++) {
                const unsigned* wb = uW + (nt * 8 + g) * WHS + ks * 8 + tg;
                MMA_TF32(ha[nt], a0, a1, a2, a3, wb[0], wb[4]);
            }
        }
#pragma unroll
        for (int nt = 0; nt < 3; nt++)
#pragma unroll
            for (int ci = 0; ci < 4; ci++) {
                int col = nt * 8 + (tg << 1) + (ci & 1);
                int r = mrowH + g + ((ci >> 1) << 3);
                int gr = rowbase + r;
                if (col < NACT)
                    pol[(size_t)gr * NACT + col] = ha[nt][ci] + bp[col];
                else if (col == NACT)
                    val[gr] = ha[nt][ci] + bv[0];
            }
    }
}

extern "C" void kernel_launch(void* const* d_in, const int* in_sizes, int n_in,
                              void* d_out, int out_size) {
    const float* x    = (const float*)d_in[0];
    const float* Wih0 = (const float*)d_in[1];
    // d_in[2] = Whh0: unused (h=0)
    const float* bih0 = (const float*)d_in[3];
    const float* bhh0 = (const float*)d_in[4];
    const float* Wih1 = (const float*)d_in[5];
    // d_in[6] = Whh1: unused (h=0)
    const float* bih1 = (const float*)d_in[7];
    const float* bhh1 = (const float*)d_in[8];
    const float* Wp   = (const float*)d_in[9];
    const float* bp   = (const float*)d_in[10];
    const float* Wv   = (const float*)d_in[11];
    const float* bv   = (const float*)d_in[12];
    float* out = (float*)d_out;

    cudaFuncSetAttribute(lstm_policy_kernel,
                         cudaFuncAttributeMaxDynamicSharedMemorySize, SMEM_BYTES);

    dim3 grid(BATCH / BM);
    dim3 block(NTHR);
    lstm_policy_kernel<<<grid, block, SMEM_BYTES>>>(
        x, Wih0, bih0, bhh0, Wih1, bih1, bhh1, Wp, bp, Wv, bv, out);
}